// round 4
// baseline (speedup 1.0000x reference)
#include <cuda_runtime.h>
#include <cuda_bf16.h>
#include <cstdint>

// Problem constants
#define B_  2
#define S_  2048
#define D_  1024
#define H_  16
#define HD_ 64
#define N3_ 3072
#define M_  (B_ * S_)   // 4096

// Scratch: fused KQV projection output [M_, 3072], per-row layout [3][H][64].
__device__ float g_kqv[(size_t)M_ * N3_];
// bf16 split operands for the tensor-core GEMM
__device__ __nv_bfloat16 g_Ah[(size_t)M_ * D_];
__device__ __nv_bfloat16 g_Al[(size_t)M_ * D_];
__device__ __nv_bfloat16 g_Wh[(size_t)N3_ * D_];   // W transposed: [n][k]
__device__ __nv_bfloat16 g_Wl[(size_t)N3_ * D_];

typedef unsigned long long ull;

// ===================== helpers =====================
__device__ __forceinline__ uint32_t smem_u32(const void* p) {
    uint32_t a;
    asm("{ .reg .u64 t; cvta.to.shared.u64 t, %1; cvt.u32.u64 %0, t; }" : "=r"(a) : "l"(p));
    return a;
}
#define SWZ(o) ((o) ^ (((o) >> 3) & 0x70))

__device__ __forceinline__ void cp_async16(uint32_t dst, const void* src) {
    asm volatile("cp.async.cg.shared.global [%0], [%1], 16;" :: "r"(dst), "l"(src));
}
__device__ __forceinline__ void cp_commit() { asm volatile("cp.async.commit_group;" ::: "memory"); }
__device__ __forceinline__ void cp_wait0()  { asm volatile("cp.async.wait_group 0;" ::: "memory"); }

__device__ __forceinline__ void ldsm_x4(uint32_t* r, uint32_t addr) {
    asm volatile("ldmatrix.sync.aligned.m8n8.x4.shared.b16 {%0,%1,%2,%3}, [%4];"
        : "=r"(r[0]), "=r"(r[1]), "=r"(r[2]), "=r"(r[3]) : "r"(addr));
}
__device__ __forceinline__ void mma_bf16(float* d, const uint32_t* a, const uint32_t* b) {
    asm volatile("mma.sync.aligned.m16n8k16.row.col.f32.bf16.bf16.f32 "
        "{%0,%1,%2,%3}, {%4,%5,%6,%7}, {%8,%9}, {%0,%1,%2,%3};"
        : "+f"(d[0]), "+f"(d[1]), "+f"(d[2]), "+f"(d[3])
        : "r"(a[0]), "r"(a[1]), "r"(a[2]), "r"(a[3]), "r"(b[0]), "r"(b[1]));
}

// fp32 pair helpers for the attention kernel
__device__ __forceinline__ ull pack2(float lo, float hi) {
    ull r; asm("mov.b64 %0, {%1,%2};" : "=l"(r) : "f"(lo), "f"(hi)); return r;
}
__device__ __forceinline__ void unpack2(ull v, float& lo, float& hi) {
    asm("mov.b64 {%0,%1}, %2;" : "=f"(lo), "=f"(hi) : "l"(v));
}
__device__ __forceinline__ ull fma2(ull a, ull b, ull c) {
    ull d; asm("fma.rn.f32x2 %0, %1, %2, %3;" : "=l"(d) : "l"(a), "l"(b), "l"(c)); return d;
}

// ============================================================================
// Split kernels: fp32 -> (hi, lo) bf16 pair
// ============================================================================
__global__ void split_a_kernel(const float* __restrict__ in) {
    size_t i = ((size_t)blockIdx.x * 256 + threadIdx.x) * 4;
    float4 v = *(const float4*)(in + i);
    float x[4] = {v.x, v.y, v.z, v.w};
    #pragma unroll
    for (int j = 0; j < 4; ++j) {
        __nv_bfloat16 h = __float2bfloat16(x[j]);
        g_Ah[i + j] = h;
        g_Al[i + j] = __float2bfloat16(x[j] - __bfloat162float(h));
    }
}

// W[k][n] fp32 -> Wh/Wl[n][k] bf16 (transpose + split), 32x32 smem tiles
__global__ void split_w_kernel(const float* __restrict__ W) {
    __shared__ float t[32][33];
    int tx = threadIdx.x, ty = threadIdx.y;
    int n0 = blockIdx.x * 32, k0 = blockIdx.y * 32;
    #pragma unroll
    for (int i = 0; i < 4; ++i)
        t[ty + i * 8][tx] = W[(size_t)(k0 + ty + i * 8) * N3_ + n0 + tx];
    __syncthreads();
    #pragma unroll
    for (int i = 0; i < 4; ++i) {
        float x = t[tx][ty + i * 8];
        size_t o = (size_t)(n0 + ty + i * 8) * D_ + k0 + tx;
        __nv_bfloat16 h = __float2bfloat16(x);
        g_Wh[o] = h;
        g_Wl[o] = __float2bfloat16(x - __bfloat162float(h));
    }
}

// ============================================================================
// HMMA GEMM: g_kqv[4096,3072] = A @ W + bias  via bf16-split (3 products).
// CTA 128x128, BK=64, 8 warps (2x4), warp tile 64x32, mma.sync m16n8k16.
// cp.async double buffer; SW128 swizzled smem; conflict-free ldmatrix.
// ============================================================================
#define GM 128
#define GN 128
#define GKC 64
#define NCHUNK (D_ / GKC)          // 16
#define OPBYTES (GM * GKC * 2)     // 16384 per operand tile
#define STAGE_BYTES (4 * OPBYTES)  // 65536
#define GEMM_SMEM (2 * STAGE_BYTES)

__global__ __launch_bounds__(256, 1) void gemm_mma_kernel(const float* __restrict__ bias)
{
    extern __shared__ char smem[];
    const uint32_t sb = smem_u32(smem);
    const int tid = threadIdx.x, lane = tid & 31, wid = tid >> 5;
    const int wm = wid & 1, wn = wid >> 1;          // warp grid 2(m) x 4(n)
    const int m0 = blockIdx.y * GM, n0 = blockIdx.x * GN;

    auto load_chunk = [&](int c, int st) {
        const size_t kb = (size_t)c * GKC;
        const uint32_t base = sb + st * STAGE_BYTES;
        #pragma unroll
        for (int i = 0; i < 4; ++i) {
            int idx = tid + i * 256;
            int r = idx >> 3, ch = idx & 7;
            uint32_t off = SWZ((uint32_t)(r * 128 + ch * 16));
            const size_t ga = (size_t)(m0 + r) * D_ + kb + ch * 8;
            const size_t gb = (size_t)(n0 + r) * D_ + kb + ch * 8;
            cp_async16(base + off,               g_Ah + ga);
            cp_async16(base + OPBYTES + off,     g_Al + ga);
            cp_async16(base + 2 * OPBYTES + off, g_Wh + gb);
            cp_async16(base + 3 * OPBYTES + off, g_Wl + gb);
        }
    };

    float acc[4][4][4];
    #pragma unroll
    for (int mt = 0; mt < 4; ++mt)
        #pragma unroll
        for (int nt = 0; nt < 4; ++nt)
            #pragma unroll
            for (int r = 0; r < 4; ++r) acc[mt][nt][r] = 0.f;

    // per-lane ldmatrix row/col pieces
    const int a_row = wm * 64 + (lane & 15);                       // + mt*16
    const int a_kb  = (lane >> 4) * 16;                            // + ks*32
    const int b_row = wn * 32 + ((lane >> 4) & 1) * 8 + (lane & 7); // + nt2*16
    const int b_kb  = ((lane >> 3) & 1) * 16;                      // + ks*32

    load_chunk(0, 0);
    cp_commit(); cp_wait0();
    __syncthreads();

    for (int kt = 0; kt < NCHUNK; ++kt) {
        const int st = kt & 1;
        if (kt + 1 < NCHUNK) { load_chunk(kt + 1, st ^ 1); cp_commit(); }

        const uint32_t base = sb + st * STAGE_BYTES;
        #pragma unroll
        for (int ks = 0; ks < 4; ++ks) {
            uint32_t ah[4][4], al[4][4], bh[2][4], bl[2][4];
            #pragma unroll
            for (int mt = 0; mt < 4; ++mt) {
                uint32_t off = SWZ((uint32_t)((a_row + mt * 16) * 128 + ks * 32 + a_kb));
                ldsm_x4(ah[mt], base + off);
                ldsm_x4(al[mt], base + OPBYTES + off);
            }
            #pragma unroll
            for (int nt2 = 0; nt2 < 2; ++nt2) {
                uint32_t off = SWZ((uint32_t)((b_row + nt2 * 16) * 128 + ks * 32 + b_kb));
                ldsm_x4(bh[nt2], base + 2 * OPBYTES + off);
                ldsm_x4(bl[nt2], base + 3 * OPBYTES + off);
            }
            #pragma unroll
            for (int mt = 0; mt < 4; ++mt)
                #pragma unroll
                for (int nt = 0; nt < 4; ++nt) {
                    const uint32_t* ph = &bh[nt >> 1][(nt & 1) * 2];
                    const uint32_t* pl = &bl[nt >> 1][(nt & 1) * 2];
                    mma_bf16(acc[mt][nt], ah[mt], ph);   // hi*hi
                    mma_bf16(acc[mt][nt], ah[mt], pl);   // hi*lo
                    mma_bf16(acc[mt][nt], al[mt], ph);   // lo*hi
                }
        }
        if (kt + 1 < NCHUNK) cp_wait0();
        __syncthreads();
    }

    // Epilogue: bias add + store. Lane holds (row=grp, col=qc..qc+1) and (row+8).
    const int grp = lane >> 2, qc = (lane & 3) * 2;
    #pragma unroll
    for (int mt = 0; mt < 4; ++mt) {
        const int r0 = m0 + wm * 64 + mt * 16 + grp;
        #pragma unroll
        for (int nt = 0; nt < 4; ++nt) {
            const int col = n0 + wn * 32 + nt * 8 + qc;
            const float2 bv = *(const float2*)(bias + col);
            float* p0 = g_kqv + (size_t)r0 * N3_ + col;
            float2 o0 = make_float2(acc[mt][nt][0] + bv.x, acc[mt][nt][1] + bv.y);
            float2 o1 = make_float2(acc[mt][nt][2] + bv.x, acc[mt][nt][3] + bv.y);
            *(float2*)p0            = o0;
            *(float2*)(p0 + 8 * (size_t)N3_) = o1;
        }
    }
}

// ============================================================================
// Fused flash-style attention (unchanged from R2: passing, crossbar-bound)
// ============================================================================
#define BQ 128
#define BK 64

__global__ __launch_bounds__(256, 2) void attn_kernel(
    const float* __restrict__ masks, float* __restrict__ out)
{
    extern __shared__ float sm[];
    float* Qs = sm;                         // 128*65
    float* Kt = Qs + 128 * 65;              // 64*66
    float* Vs = Kt + 64 * 66;               // 64*64
    float* Ps = Vs + 64 * 64;               // 128*65
    float* mk = Ps + 128 * 65;              // 64

    const int tid = threadIdx.x;
    const int tx = tid & 7, ty = tid >> 3;
    const int b = blockIdx.z, h = blockIdx.y;
    const int q0g = blockIdx.x * BQ;

    const float* Qg = g_kqv + (size_t)(b * S_ + q0g) * N3_ + D_ + h * HD_;
    const float* Kg = g_kqv + (size_t)(b * S_) * N3_ + h * HD_;
    const float* Vg = g_kqv + (size_t)(b * S_) * N3_ + 2 * D_ + h * HD_;

    #pragma unroll
    for (int it = 0; it < 8; ++it) {
        int idx = it * 256 + tid;
        int q = idx >> 4, d4 = (idx & 15) * 4;
        float4 v = *(const float4*)(Qg + (size_t)q * N3_ + d4);
        Qs[q * 65 + d4 + 0] = v.x; Qs[q * 65 + d4 + 1] = v.y;
        Qs[q * 65 + d4 + 2] = v.z; Qs[q * 65 + d4 + 3] = v.w;
    }

    ull acc2[4][4];
    #pragma unroll
    for (int i = 0; i < 4; ++i)
        #pragma unroll
        for (int j = 0; j < 4; ++j) acc2[i][j] = 0ull;
    float den[4] = {0.f, 0.f, 0.f, 0.f};

    float4 kr[4], vr[4]; float mreg;
    #pragma unroll
    for (int it = 0; it < 4; ++it) {
        int idx = it * 256 + tid;
        int k = idx >> 4, d4 = (idx & 15) * 4;
        kr[it] = *(const float4*)(Kg + (size_t)k * N3_ + d4);
        vr[it] = *(const float4*)(Vg + (size_t)k * N3_ + d4);
    }
    mreg = (tid < BK) ? masks[b * S_ + tid] : 0.f;

    for (int kt = 0; kt < S_ / BK; ++kt) {
        #pragma unroll
        for (int it = 0; it < 4; ++it) {
            int idx = it * 256 + tid;
            int k = idx >> 4, d4 = (idx & 15) * 4;
            Kt[(d4 + 0) * 66 + k] = kr[it].x;
            Kt[(d4 + 1) * 66 + k] = kr[it].y;
            Kt[(d4 + 2) * 66 + k] = kr[it].z;
            Kt[(d4 + 3) * 66 + k] = kr[it].w;
            *(float4*)&Vs[k * 64 + d4] = vr[it];
        }
        if (tid < BK) mk[tid] = mreg;
        __syncthreads();

        ull s2[4][4];
        #pragma unroll
        for (int i = 0; i < 4; ++i)
            #pragma unroll
            for (int j = 0; j < 4; ++j) s2[i][j] = 0ull;

        #pragma unroll 8
        for (int dd = 0; dd < HD_; ++dd) {
            ull b2[4];
            #pragma unroll
            for (int j = 0; j < 4; ++j)
                b2[j] = *(const ull*)&Kt[dd * 66 + tx * 8 + 2 * j];
            #pragma unroll
            for (int i = 0; i < 4; ++i) {
                float a = Qs[(ty * 4 + i) * 65 + dd];
                ull ad = pack2(a, a);
                #pragma unroll
                for (int j = 0; j < 4; ++j) s2[i][j] = fma2(ad, b2[j], s2[i][j]);
            }
        }

        float r[4];
        #pragma unroll
        for (int i = 0; i < 4; ++i) {
            r[i] = 0.f;
            #pragma unroll
            for (int j = 0; j < 4; ++j) {
                float lo, hi; unpack2(s2[i][j], lo, hi);
                float e0 = lo > 0.f ? fminf(lo, 10.f) : (__expf(lo) - 1.f);
                float e1 = hi > 0.f ? fminf(hi, 10.f) : (__expf(hi) - 1.f);
                float p0 = __expf(e0) * mk[tx * 8 + 2 * j];
                float p1 = __expf(e1) * mk[tx * 8 + 2 * j + 1];
                Ps[(ty * 4 + i) * 65 + tx * 8 + 2 * j]     = p0;
                Ps[(ty * 4 + i) * 65 + tx * 8 + 2 * j + 1] = p1;
                r[i] += p0 + p1;
            }
        }
        #pragma unroll
        for (int i = 0; i < 4; ++i) {
            float v = r[i];
            v += __shfl_xor_sync(0xffffffffu, v, 1);
            v += __shfl_xor_sync(0xffffffffu, v, 2);
            v += __shfl_xor_sync(0xffffffffu, v, 4);
            den[i] += v;
        }
        __syncthreads();

        if (kt + 1 < S_ / BK) {
            #pragma unroll
            for (int it = 0; it < 4; ++it) {
                int idx = it * 256 + tid;
                int k = idx >> 4, d4 = (idx & 15) * 4;
                kr[it] = *(const float4*)(Kg + (size_t)((kt + 1) * BK + k) * N3_ + d4);
                vr[it] = *(const float4*)(Vg + (size_t)((kt + 1) * BK + k) * N3_ + d4);
            }
            mreg = (tid < BK) ? masks[b * S_ + (kt + 1) * BK + tid] : 0.f;
        }

        #pragma unroll 4
        for (int kk = 0; kk < BK; ++kk) {
            ull v2[4];
            #pragma unroll
            for (int j = 0; j < 4; ++j)
                v2[j] = *(const ull*)&Vs[kk * 64 + tx * 8 + 2 * j];
            #pragma unroll
            for (int i = 0; i < 4; ++i) {
                float p = Ps[(ty * 4 + i) * 65 + kk];
                ull pd = pack2(p, p);
                #pragma unroll
                for (int j = 0; j < 4; ++j) acc2[i][j] = fma2(pd, v2[j], acc2[i][j]);
            }
        }
        __syncthreads();
    }

    #pragma unroll
    for (int i = 0; i < 4; ++i) {
        int q = q0g + ty * 4 + i;
        float scale = masks[b * S_ + q] / den[i];
        float o[8];
        #pragma unroll
        for (int j = 0; j < 4; ++j) unpack2(acc2[i][j], o[2 * j], o[2 * j + 1]);
        float* op = out + (size_t)(b * S_ + q) * D_ + h * HD_ + tx * 8;
        *(float4*)op       = make_float4(o[0] * scale, o[1] * scale, o[2] * scale, o[3] * scale);
        *(float4*)(op + 4) = make_float4(o[4] * scale, o[5] * scale, o[6] * scale, o[7] * scale);
    }
}

// ============================================================================
// Launch
// ============================================================================
extern "C" void kernel_launch(void* const* d_in, const int* in_sizes, int n_in,
                              void* d_out, int out_size)
{
    const float *inp = nullptr, *msk = nullptr, *W = nullptr, *bias = nullptr;
    for (int i = 0; i < n_in; ++i) {
        switch (in_sizes[i]) {
            case M_ * D_:   inp  = (const float*)d_in[i]; break;  // inputs  [2,2048,1024]
            case B_ * S_:   msk  = (const float*)d_in[i]; break;  // masks   [2,2048]
            case D_ * N3_:  W    = (const float*)d_in[i]; break;  // W       [1024,3072]
            case N3_:       bias = (const float*)d_in[i]; break;  // b       [3072]
        }
    }

    cudaFuncSetAttribute(gemm_mma_kernel,
                         cudaFuncAttributeMaxDynamicSharedMemorySize, GEMM_SMEM);
    cudaFuncSetAttribute(attn_kernel,
                         cudaFuncAttributeMaxDynamicSharedMemorySize, 100096);

    split_a_kernel<<<(M_ * D_) / 1024, 256>>>(inp);
    split_w_kernel<<<dim3(N3_ / 32, D_ / 32), dim3(32, 8)>>>(W);

    dim3 g1(N3_ / GN, M_ / GM);            // (24, 32)
    gemm_mma_kernel<<<g1, 256, GEMM_SMEM>>>(bias);

    dim3 g2(S_ / BQ, H_, B_);              // (16, 16, 2)
    attn_kernel<<<g2, 256, 100096>>>(msk, (float*)d_out);
}

// round 5
// speedup vs baseline: 3.7015x; 3.7015x over previous
#include <cuda_runtime.h>
#include <cuda_bf16.h>
#include <cstdint>

// Problem constants
#define B_  2
#define S_  2048
#define D_  1024
#define H_  16
#define HD_ 64
#define N3_ 3072
#define M_  (B_ * S_)   // 4096

// bf16 hi/lo pairs: split inputs for projection GEMM, and split KQV output.
__device__ __nv_bfloat16 g_Ah[(size_t)M_ * D_];
__device__ __nv_bfloat16 g_Al[(size_t)M_ * D_];
__device__ __nv_bfloat16 g_Wh[(size_t)N3_ * D_];   // W transposed: [n][k]
__device__ __nv_bfloat16 g_Wl[(size_t)N3_ * D_];
__device__ __nv_bfloat16 g_kqvh[(size_t)M_ * N3_]; // [token][3072]: K|Q|V
__device__ __nv_bfloat16 g_kqvl[(size_t)M_ * N3_];

typedef unsigned long long ull;

// ===================== helpers =====================
__device__ __forceinline__ uint32_t smem_u32(const void* p) {
    uint32_t a;
    asm("{ .reg .u64 t; cvta.to.shared.u64 t, %1; cvt.u32.u64 %0, t; }" : "=r"(a) : "l"(p));
    return a;
}
#define SWZ(o) ((o) ^ (((o) >> 3) & 0x70))

__device__ __forceinline__ void cp_async16(uint32_t dst, const void* src) {
    asm volatile("cp.async.cg.shared.global [%0], [%1], 16;" :: "r"(dst), "l"(src));
}
__device__ __forceinline__ void cp_async4(uint32_t dst, const void* src) {
    asm volatile("cp.async.ca.shared.global [%0], [%1], 4;" :: "r"(dst), "l"(src));
}
__device__ __forceinline__ void cp_commit() { asm volatile("cp.async.commit_group;" ::: "memory"); }
__device__ __forceinline__ void cp_wait0()  { asm volatile("cp.async.wait_group 0;" ::: "memory"); }

__device__ __forceinline__ void ldsm_x4(uint32_t* r, uint32_t addr) {
    asm volatile("ldmatrix.sync.aligned.m8n8.x4.shared.b16 {%0,%1,%2,%3}, [%4];"
        : "=r"(r[0]), "=r"(r[1]), "=r"(r[2]), "=r"(r[3]) : "r"(addr));
}
__device__ __forceinline__ void ldsm_x4_t(uint32_t* r, uint32_t addr) {
    asm volatile("ldmatrix.sync.aligned.m8n8.x4.trans.shared.b16 {%0,%1,%2,%3}, [%4];"
        : "=r"(r[0]), "=r"(r[1]), "=r"(r[2]), "=r"(r[3]) : "r"(addr));
}
__device__ __forceinline__ void mma_bf16(float* d, const uint32_t* a, const uint32_t* b) {
    asm volatile("mma.sync.aligned.m16n8k16.row.col.f32.bf16.bf16.f32 "
        "{%0,%1,%2,%3}, {%4,%5,%6,%7}, {%8,%9}, {%0,%1,%2,%3};"
        : "+f"(d[0]), "+f"(d[1]), "+f"(d[2]), "+f"(d[3])
        : "r"(a[0]), "r"(a[1]), "r"(a[2]), "r"(a[3]), "r"(b[0]), "r"(b[1]));
}

// pack two fp32 into bf16 hi-pair + lo-pair (residual)
__device__ __forceinline__ void split2(float a, float b, uint32_t& h2, uint32_t& l2) {
    __nv_bfloat162 h;
    h.x = __float2bfloat16(a); h.y = __float2bfloat16(b);
    __nv_bfloat162 l;
    l.x = __float2bfloat16(a - __bfloat162float(h.x));
    l.y = __float2bfloat16(b - __bfloat162float(h.y));
    h2 = *(uint32_t*)&h; l2 = *(uint32_t*)&l;
}

__device__ __forceinline__ float elu_exp(float u) {
    float e = u > 0.f ? fminf(u, 10.f) : (__expf(u) - 1.f);
    return __expf(e);
}

// ============================================================================
// Split kernels: fp32 -> (hi, lo) bf16 pair
// ============================================================================
__global__ void split_a_kernel(const float* __restrict__ in) {
    size_t i = ((size_t)blockIdx.x * 256 + threadIdx.x) * 4;
    float4 v = *(const float4*)(in + i);
    float x[4] = {v.x, v.y, v.z, v.w};
    #pragma unroll
    for (int j = 0; j < 4; ++j) {
        __nv_bfloat16 h = __float2bfloat16(x[j]);
        g_Ah[i + j] = h;
        g_Al[i + j] = __float2bfloat16(x[j] - __bfloat162float(h));
    }
}

__global__ void split_w_kernel(const float* __restrict__ W) {
    __shared__ float t[32][33];
    int tx = threadIdx.x, ty = threadIdx.y;
    int n0 = blockIdx.x * 32, k0 = blockIdx.y * 32;
    #pragma unroll
    for (int i = 0; i < 4; ++i)
        t[ty + i * 8][tx] = W[(size_t)(k0 + ty + i * 8) * N3_ + n0 + tx];
    __syncthreads();
    #pragma unroll
    for (int i = 0; i < 4; ++i) {
        float x = t[tx][ty + i * 8];
        size_t o = (size_t)(n0 + ty + i * 8) * D_ + k0 + tx;
        __nv_bfloat16 h = __float2bfloat16(x);
        g_Wh[o] = h;
        g_Wl[o] = __float2bfloat16(x - __bfloat162float(h));
    }
}

// ============================================================================
// HMMA projection GEMM: kqv = A @ W + bias, output written as bf16 hi/lo.
// CTA 128x128, BK=64, 8 warps (2x4), warp tile 64x32, mma.sync m16n8k16.
// ============================================================================
#define GM 128
#define GN 128
#define GKC 64
#define NCHUNK (D_ / GKC)          // 16
#define OPBYTES (GM * GKC * 2)     // 16384 per operand tile
#define STAGE_BYTES (4 * OPBYTES)  // 65536
#define GEMM_SMEM (2 * STAGE_BYTES)

__global__ __launch_bounds__(256, 1) void gemm_mma_kernel(const float* __restrict__ bias)
{
    extern __shared__ char smem[];
    const uint32_t sb = smem_u32(smem);
    const int tid = threadIdx.x, lane = tid & 31, wid = tid >> 5;
    const int wm = wid & 1, wn = wid >> 1;
    const int m0 = blockIdx.y * GM, n0 = blockIdx.x * GN;

    auto load_chunk = [&](int c, int st) {
        const size_t kb = (size_t)c * GKC;
        const uint32_t base = sb + st * STAGE_BYTES;
        #pragma unroll
        for (int i = 0; i < 4; ++i) {
            int idx = tid + i * 256;
            int r = idx >> 3, ch = idx & 7;
            uint32_t off = SWZ((uint32_t)(r * 128 + ch * 16));
            const size_t ga = (size_t)(m0 + r) * D_ + kb + ch * 8;
            const size_t gb = (size_t)(n0 + r) * D_ + kb + ch * 8;
            cp_async16(base + off,               g_Ah + ga);
            cp_async16(base + OPBYTES + off,     g_Al + ga);
            cp_async16(base + 2 * OPBYTES + off, g_Wh + gb);
            cp_async16(base + 3 * OPBYTES + off, g_Wl + gb);
        }
    };

    float acc[4][4][4];
    #pragma unroll
    for (int mt = 0; mt < 4; ++mt)
        #pragma unroll
        for (int nt = 0; nt < 4; ++nt)
            #pragma unroll
            for (int r = 0; r < 4; ++r) acc[mt][nt][r] = 0.f;

    const int a_row = wm * 64 + (lane & 15);
    const int a_kb  = (lane >> 4) * 16;
    const int b_row = wn * 32 + ((lane >> 4) & 1) * 8 + (lane & 7);
    const int b_kb  = ((lane >> 3) & 1) * 16;

    load_chunk(0, 0);
    cp_commit(); cp_wait0();
    __syncthreads();

    for (int kt = 0; kt < NCHUNK; ++kt) {
        const int st = kt & 1;
        if (kt + 1 < NCHUNK) { load_chunk(kt + 1, st ^ 1); cp_commit(); }

        const uint32_t base = sb + st * STAGE_BYTES;
        #pragma unroll
        for (int ks = 0; ks < 4; ++ks) {
            uint32_t ah[4][4], al[4][4], bh[2][4], bl[2][4];
            #pragma unroll
            for (int mt = 0; mt < 4; ++mt) {
                uint32_t off = SWZ((uint32_t)((a_row + mt * 16) * 128 + ks * 32 + a_kb));
                ldsm_x4(ah[mt], base + off);
                ldsm_x4(al[mt], base + OPBYTES + off);
            }
            #pragma unroll
            for (int nt2 = 0; nt2 < 2; ++nt2) {
                uint32_t off = SWZ((uint32_t)((b_row + nt2 * 16) * 128 + ks * 32 + b_kb));
                ldsm_x4(bh[nt2], base + 2 * OPBYTES + off);
                ldsm_x4(bl[nt2], base + 3 * OPBYTES + off);
            }
            #pragma unroll
            for (int mt = 0; mt < 4; ++mt)
                #pragma unroll
                for (int nt = 0; nt < 4; ++nt) {
                    const uint32_t* ph = &bh[nt >> 1][(nt & 1) * 2];
                    const uint32_t* pl = &bl[nt >> 1][(nt & 1) * 2];
                    mma_bf16(acc[mt][nt], ah[mt], ph);
                    mma_bf16(acc[mt][nt], ah[mt], pl);
                    mma_bf16(acc[mt][nt], al[mt], ph);
                }
        }
        if (kt + 1 < NCHUNK) cp_wait0();
        __syncthreads();
    }

    // Epilogue: bias add, split to bf16 hi/lo, store.
    const int grp = lane >> 2, qc = (lane & 3) * 2;
    #pragma unroll
    for (int mt = 0; mt < 4; ++mt) {
        const int r0 = m0 + wm * 64 + mt * 16 + grp;
        #pragma unroll
        for (int nt = 0; nt < 4; ++nt) {
            const int col = n0 + wn * 32 + nt * 8 + qc;
            const float2 bv = *(const float2*)(bias + col);
            float o0 = acc[mt][nt][0] + bv.x, o1 = acc[mt][nt][1] + bv.y;
            float o2 = acc[mt][nt][2] + bv.x, o3 = acc[mt][nt][3] + bv.y;
            uint32_t h2, l2;
            size_t off0 = (size_t)r0 * N3_ + col;
            split2(o0, o1, h2, l2);
            *(uint32_t*)(g_kqvh + off0) = h2;
            *(uint32_t*)(g_kqvl + off0) = l2;
            size_t off1 = off0 + 8 * (size_t)N3_;
            split2(o2, o3, h2, l2);
            *(uint32_t*)(g_kqvh + off1) = h2;
            *(uint32_t*)(g_kqvl + off1) = l2;
        }
    }
}

// ============================================================================
// Tensor-core flash attention.
// CTA = (b, h, 128-q tile). BK=64 key tiles, double-buffered K/V hi/lo.
// Score: Qh*Kh + Qh*Kl + Ql*Kh (mma m16n8k16). Epilogue: exp(clip(elu)))*mask,
// fp32 row-denominator in regs, P -> smem as bf16 hi/lo. PV: 3 products,
// V fragments via ldmatrix.trans. Out = (P@V)/den * mask_q.
// ============================================================================
#define BQ 128
#define BK 64
#define NKT (S_ / BK)     // 32

// smem byte offsets
#define QH_OFF 0
#define QL_OFF 16384
#define KH_OFF 32768      // + st*8192
#define KL_OFF 49152      // + st*8192
#define VH_OFF 65536      // + st*8192
#define VL_OFF 81920      // + st*8192
#define PH_OFF 98304
#define PL_OFF 114688
#define MK_OFF 131072     // + st*256
#define DEN_OFF 131584    // float[4][128]
#define ATTN_SMEM 133632

__global__ __launch_bounds__(256, 1) void attn_mma_kernel(
    const float* __restrict__ masks, float* __restrict__ out)
{
    extern __shared__ char smem[];
    const uint32_t sb = smem_u32(smem);
    const int tid = threadIdx.x, lane = tid & 31, wid = tid >> 5;
    const int wm = wid & 1, wn = wid >> 1;
    const int b = blockIdx.z, h = blockIdx.y;
    const int q0 = blockIdx.x * BQ;
    const int grp = lane >> 2, qc = (lane & 3) * 2;

    // fragment address pieces
    const int a_row = wm * 64 + (lane & 15);
    const int a_kb  = (lane >> 4) * 16;
    const int bk_row = wn * 16 + ((lane >> 4) & 1) * 8 + (lane & 7);  // keys 0..63
    const int bk_kb  = ((lane >> 3) & 1) * 16;
    const int v_row  = ((lane >> 3) & 1) * 8 + (lane & 7);            // + ks*16
    const int v_col  = (wn * 16 + ((lane >> 4) & 1) * 8) * 2;         // dd bytes

    auto load_kv = [&](int kt2, int st2) {
        const size_t tok0 = (size_t)(b * S_) + kt2 * BK;
        #pragma unroll
        for (int i = 0; i < 2; ++i) {
            int idx = tid + i * 256;
            int r = idx >> 3, ch = idx & 7;
            uint32_t off = SWZ((uint32_t)(r * 128 + ch * 16));
            size_t g = (tok0 + r) * N3_ + h * HD_ + ch * 8;
            cp_async16(sb + KH_OFF + st2 * 8192 + off, g_kqvh + g);
            cp_async16(sb + KL_OFF + st2 * 8192 + off, g_kqvl + g);
            cp_async16(sb + VH_OFF + st2 * 8192 + off, g_kqvh + g + 2 * D_);
            cp_async16(sb + VL_OFF + st2 * 8192 + off, g_kqvl + g + 2 * D_);
        }
        if (tid < BK)
            cp_async4(sb + MK_OFF + st2 * 256 + tid * 4, masks + (size_t)b * S_ + kt2 * BK + tid);
    };

    // Q tile (hi/lo), 128 rows x 128B each
    #pragma unroll
    for (int i = 0; i < 4; ++i) {
        int idx = tid + i * 256;
        int r = idx >> 3, ch = idx & 7;
        uint32_t off = SWZ((uint32_t)(r * 128 + ch * 16));
        size_t g = (size_t)(b * S_ + q0 + r) * N3_ + D_ + h * HD_ + ch * 8;
        cp_async16(sb + QH_OFF + off, g_kqvh + g);
        cp_async16(sb + QL_OFF + off, g_kqvl + g);
    }
    load_kv(0, 0);
    cp_commit(); cp_wait0();
    __syncthreads();

    float acc_o[4][2][4];
    #pragma unroll
    for (int mt = 0; mt < 4; ++mt)
        #pragma unroll
        for (int nt = 0; nt < 2; ++nt)
            #pragma unroll
            for (int r = 0; r < 4; ++r) acc_o[mt][nt][r] = 0.f;
    float den[4][2];
    #pragma unroll
    for (int mt = 0; mt < 4; ++mt) { den[mt][0] = 0.f; den[mt][1] = 0.f; }

    for (int kt = 0; kt < NKT; ++kt) {
        const int st = kt & 1;
        if (kt + 1 < NKT) { load_kv(kt + 1, st ^ 1); cp_commit(); }

        // ---- score GEMM: S[128 q][64 k] over d=64 ----
        float acc_s[4][2][4];
        #pragma unroll
        for (int mt = 0; mt < 4; ++mt)
            #pragma unroll
            for (int nt = 0; nt < 2; ++nt)
                #pragma unroll
                for (int r = 0; r < 4; ++r) acc_s[mt][nt][r] = 0.f;

        #pragma unroll
        for (int ks = 0; ks < 4; ++ks) {
            uint32_t aqh[4][4], aql[4][4], bkh[4], bkl[4];
            #pragma unroll
            for (int mt = 0; mt < 4; ++mt) {
                uint32_t off = SWZ((uint32_t)((a_row + mt * 16) * 128 + ks * 32 + a_kb));
                ldsm_x4(aqh[mt], sb + QH_OFF + off);
                ldsm_x4(aql[mt], sb + QL_OFF + off);
            }
            {
                uint32_t off = SWZ((uint32_t)(bk_row * 128 + ks * 32 + bk_kb));
                ldsm_x4(bkh, sb + KH_OFF + st * 8192 + off);
                ldsm_x4(bkl, sb + KL_OFF + st * 8192 + off);
            }
            #pragma unroll
            for (int mt = 0; mt < 4; ++mt)
                #pragma unroll
                for (int nt = 0; nt < 2; ++nt) {
                    mma_bf16(acc_s[mt][nt], aqh[mt], &bkh[nt * 2]);
                    mma_bf16(acc_s[mt][nt], aqh[mt], &bkl[nt * 2]);
                    mma_bf16(acc_s[mt][nt], aql[mt], &bkh[nt * 2]);
                }
        }

        // ---- epilogue: p = exp(clip(elu(s))) * mask_k; den accum; P -> smem ----
        const float* mk = (const float*)(smem + MK_OFF + st * 256);
        char* phs = smem + PH_OFF;
        char* pls = smem + PL_OFF;
        #pragma unroll
        for (int mt = 0; mt < 4; ++mt) {
            const int r = wm * 64 + mt * 16 + grp;
            #pragma unroll
            for (int nt = 0; nt < 2; ++nt) {
                const int c = wn * 16 + nt * 8 + qc;
                float m0 = mk[c], m1 = mk[c + 1];
                float p0 = elu_exp(acc_s[mt][nt][0]) * m0;
                float p1 = elu_exp(acc_s[mt][nt][1]) * m1;
                float p2 = elu_exp(acc_s[mt][nt][2]) * m0;
                float p3 = elu_exp(acc_s[mt][nt][3]) * m1;
                den[mt][0] += p0 + p1;
                den[mt][1] += p2 + p3;
                uint32_t h2, l2;
                uint32_t o0 = SWZ((uint32_t)(r * 128 + c * 2));
                split2(p0, p1, h2, l2);
                *(uint32_t*)(phs + o0) = h2;
                *(uint32_t*)(pls + o0) = l2;
                uint32_t o1 = SWZ((uint32_t)((r + 8) * 128 + c * 2));
                split2(p2, p3, h2, l2);
                *(uint32_t*)(phs + o1) = h2;
                *(uint32_t*)(pls + o1) = l2;
            }
        }
        __syncthreads();

        // ---- PV GEMM: O[128 q][64 d] += P[128][64] @ V[64][64] ----
        #pragma unroll
        for (int ks = 0; ks < 4; ++ks) {
            uint32_t aph[4][4], apl[4][4], bvh[4], bvl[4];
            #pragma unroll
            for (int mt = 0; mt < 4; ++mt) {
                uint32_t off = SWZ((uint32_t)((a_row + mt * 16) * 128 + ks * 32 + a_kb));
                ldsm_x4(aph[mt], sb + PH_OFF + off);
                ldsm_x4(apl[mt], sb + PL_OFF + off);
            }
            {
                uint32_t off = SWZ((uint32_t)((ks * 16 + v_row) * 128 + v_col));
                ldsm_x4_t(bvh, sb + VH_OFF + st * 8192 + off);
                ldsm_x4_t(bvl, sb + VL_OFF + st * 8192 + off);
            }
            #pragma unroll
            for (int mt = 0; mt < 4; ++mt)
                #pragma unroll
                for (int nt = 0; nt < 2; ++nt) {
                    mma_bf16(acc_o[mt][nt], aph[mt], &bvh[nt * 2]);
                    mma_bf16(acc_o[mt][nt], aph[mt], &bvl[nt * 2]);
                    mma_bf16(acc_o[mt][nt], apl[mt], &bvh[nt * 2]);
                }
        }
        if (kt + 1 < NKT) cp_wait0();
        __syncthreads();
    }

    // ---- denominator reduce + writeback ----
    #pragma unroll
    for (int mt = 0; mt < 4; ++mt)
        #pragma unroll
        for (int r01 = 0; r01 < 2; ++r01) {
            float v = den[mt][r01];
            v += __shfl_xor_sync(0xffffffffu, v, 1);
            v += __shfl_xor_sync(0xffffffffu, v, 2);
            den[mt][r01] = v;
        }
    float* den_s = (float*)(smem + DEN_OFF);
    if ((lane & 3) == 0) {
        #pragma unroll
        for (int mt = 0; mt < 4; ++mt) {
            int r = wm * 64 + mt * 16 + grp;
            den_s[wn * 128 + r]     = den[mt][0];
            den_s[wn * 128 + r + 8] = den[mt][1];
        }
    }
    __syncthreads();

    #pragma unroll
    for (int mt = 0; mt < 4; ++mt) {
        const int r = wm * 64 + mt * 16 + grp;
        float d0 = den_s[r] + den_s[128 + r] + den_s[256 + r] + den_s[384 + r];
        float d1 = den_s[r + 8] + den_s[128 + r + 8] + den_s[256 + r + 8] + den_s[384 + r + 8];
        float s0 = masks[(size_t)b * S_ + q0 + r]     / d0;
        float s1 = masks[(size_t)b * S_ + q0 + r + 8] / d1;
        #pragma unroll
        for (int nt = 0; nt < 2; ++nt) {
            const int c = wn * 16 + nt * 8 + qc;
            float* p0 = out + (size_t)(b * S_ + q0 + r) * D_ + h * HD_ + c;
            *(float2*)p0 = make_float2(acc_o[mt][nt][0] * s0, acc_o[mt][nt][1] * s0);
            *(float2*)(p0 + 8 * (size_t)D_) =
                make_float2(acc_o[mt][nt][2] * s1, acc_o[mt][nt][3] * s1);
        }
    }
}

// ============================================================================
// Launch
// ============================================================================
extern "C" void kernel_launch(void* const* d_in, const int* in_sizes, int n_in,
                              void* d_out, int out_size)
{
    const float *inp = nullptr, *msk = nullptr, *W = nullptr, *bias = nullptr;
    for (int i = 0; i < n_in; ++i) {
        switch (in_sizes[i]) {
            case M_ * D_:   inp  = (const float*)d_in[i]; break;  // inputs  [2,2048,1024]
            case B_ * S_:   msk  = (const float*)d_in[i]; break;  // masks   [2,2048]
            case D_ * N3_:  W    = (const float*)d_in[i]; break;  // W       [1024,3072]
            case N3_:       bias = (const float*)d_in[i]; break;  // b       [3072]
        }
    }

    cudaFuncSetAttribute(gemm_mma_kernel,
                         cudaFuncAttributeMaxDynamicSharedMemorySize, GEMM_SMEM);
    cudaFuncSetAttribute(attn_mma_kernel,
                         cudaFuncAttributeMaxDynamicSharedMemorySize, ATTN_SMEM);

    split_a_kernel<<<(M_ * D_) / 1024, 256>>>(inp);
    split_w_kernel<<<dim3(N3_ / 32, D_ / 32), dim3(32, 8)>>>(W);

    dim3 g1(N3_ / GN, M_ / GM);            // (24, 32)
    gemm_mma_kernel<<<g1, 256, GEMM_SMEM>>>(bias);

    dim3 g2(S_ / BQ, H_, B_);              // (16, 16, 2)
    attn_mma_kernel<<<g2, 256, ATTN_SMEM>>>(msk, (float*)d_out);
}

// round 6
// speedup vs baseline: 4.4415x; 1.1999x over previous
#include <cuda_runtime.h>
#include <cuda_bf16.h>
#include <cstdint>

// Problem constants
#define B_  2
#define S_  2048
#define D_  1024
#define H_  16
#define HD_ 64
#define N3_ 3072
#define M_  (B_ * S_)   // 4096

// bf16 hi/lo pairs: split inputs for projection GEMM, and split KQV output.
__device__ __nv_bfloat16 g_Ah[(size_t)M_ * D_];
__device__ __nv_bfloat16 g_Al[(size_t)M_ * D_];
__device__ __nv_bfloat16 g_Wh[(size_t)N3_ * D_];   // W transposed: [n][k]
__device__ __nv_bfloat16 g_Wl[(size_t)N3_ * D_];
__device__ __nv_bfloat16 g_kqvh[(size_t)M_ * N3_]; // [token][3072]: K|Q|V
__device__ __nv_bfloat16 g_kqvl[(size_t)M_ * N3_];

typedef unsigned long long ull;

// ===================== helpers =====================
__device__ __forceinline__ uint32_t smem_u32(const void* p) {
    uint32_t a;
    asm("{ .reg .u64 t; cvta.to.shared.u64 t, %1; cvt.u32.u64 %0, t; }" : "=r"(a) : "l"(p));
    return a;
}
#define SWZ(o) ((o) ^ (((o) >> 3) & 0x70))

__device__ __forceinline__ void cp_async16(uint32_t dst, const void* src) {
    asm volatile("cp.async.cg.shared.global [%0], [%1], 16;" :: "r"(dst), "l"(src));
}
__device__ __forceinline__ void cp_async4(uint32_t dst, const void* src) {
    asm volatile("cp.async.ca.shared.global [%0], [%1], 4;" :: "r"(dst), "l"(src));
}
__device__ __forceinline__ void cp_commit() { asm volatile("cp.async.commit_group;" ::: "memory"); }
__device__ __forceinline__ void cp_wait0()  { asm volatile("cp.async.wait_group 0;" ::: "memory"); }
__device__ __forceinline__ void cp_wait1()  { asm volatile("cp.async.wait_group 1;" ::: "memory"); }

__device__ __forceinline__ void ldsm_x4(uint32_t* r, uint32_t addr) {
    asm volatile("ldmatrix.sync.aligned.m8n8.x4.shared.b16 {%0,%1,%2,%3}, [%4];"
        : "=r"(r[0]), "=r"(r[1]), "=r"(r[2]), "=r"(r[3]) : "r"(addr));
}
__device__ __forceinline__ void ldsm_x4_t(uint32_t* r, uint32_t addr) {
    asm volatile("ldmatrix.sync.aligned.m8n8.x4.trans.shared.b16 {%0,%1,%2,%3}, [%4];"
        : "=r"(r[0]), "=r"(r[1]), "=r"(r[2]), "=r"(r[3]) : "r"(addr));
}
__device__ __forceinline__ void mma_bf16(float* d, const uint32_t* a, const uint32_t* b) {
    asm volatile("mma.sync.aligned.m16n8k16.row.col.f32.bf16.bf16.f32 "
        "{%0,%1,%2,%3}, {%4,%5,%6,%7}, {%8,%9}, {%0,%1,%2,%3};"
        : "+f"(d[0]), "+f"(d[1]), "+f"(d[2]), "+f"(d[3])
        : "r"(a[0]), "r"(a[1]), "r"(a[2]), "r"(a[3]), "r"(b[0]), "r"(b[1]));
}

// pack two fp32 into bf16 hi-pair + lo-pair (residual)
__device__ __forceinline__ void split2(float a, float b, uint32_t& h2, uint32_t& l2) {
    __nv_bfloat162 h;
    h.x = __float2bfloat16(a); h.y = __float2bfloat16(b);
    __nv_bfloat162 l;
    l.x = __float2bfloat16(a - __bfloat162float(h.x));
    l.y = __float2bfloat16(b - __bfloat162float(h.y));
    h2 = *(uint32_t*)&h; l2 = *(uint32_t*)&l;
}

__device__ __forceinline__ float elu_exp(float u) {
    float e = u > 0.f ? fminf(u, 10.f) : (__expf(u) - 1.f);
    return __expf(e);
}

// ============================================================================
// Split kernels: fp32 -> (hi, lo) bf16 pair
// ============================================================================
__global__ void split_a_kernel(const float* __restrict__ in) {
    size_t i = ((size_t)blockIdx.x * 256 + threadIdx.x) * 4;
    float4 v = *(const float4*)(in + i);
    float x[4] = {v.x, v.y, v.z, v.w};
    #pragma unroll
    for (int j = 0; j < 4; ++j) {
        __nv_bfloat16 h = __float2bfloat16(x[j]);
        g_Ah[i + j] = h;
        g_Al[i + j] = __float2bfloat16(x[j] - __bfloat162float(h));
    }
}

__global__ void split_w_kernel(const float* __restrict__ W) {
    __shared__ float t[32][33];
    int tx = threadIdx.x, ty = threadIdx.y;
    int n0 = blockIdx.x * 32, k0 = blockIdx.y * 32;
    #pragma unroll
    for (int i = 0; i < 4; ++i)
        t[ty + i * 8][tx] = W[(size_t)(k0 + ty + i * 8) * N3_ + n0 + tx];
    __syncthreads();
    #pragma unroll
    for (int i = 0; i < 4; ++i) {
        float x = t[tx][ty + i * 8];
        size_t o = (size_t)(n0 + ty + i * 8) * D_ + k0 + tx;
        __nv_bfloat16 h = __float2bfloat16(x);
        g_Wh[o] = h;
        g_Wl[o] = __float2bfloat16(x - __bfloat162float(h));
    }
}

// ============================================================================
// HMMA projection GEMM: kqv = A @ W + bias, output written as bf16 hi/lo.
// CTA 128x128, BK=64, 8 warps (2x4), warp tile 64x32, mma.sync m16n8k16.
// ============================================================================
#define GM 128
#define GN 128
#define GKC 64
#define NCHUNK (D_ / GKC)          // 16
#define OPBYTES (GM * GKC * 2)     // 16384 per operand tile
#define STAGE_BYTES (4 * OPBYTES)  // 65536
#define GEMM_SMEM (2 * STAGE_BYTES)

__global__ __launch_bounds__(256, 1) void gemm_mma_kernel(const float* __restrict__ bias)
{
    extern __shared__ char smem[];
    const uint32_t sb = smem_u32(smem);
    const int tid = threadIdx.x, lane = tid & 31, wid = tid >> 5;
    const int wm = wid & 1, wn = wid >> 1;
    const int m0 = blockIdx.y * GM, n0 = blockIdx.x * GN;

    auto load_chunk = [&](int c, int st) {
        const size_t kb = (size_t)c * GKC;
        const uint32_t base = sb + st * STAGE_BYTES;
        #pragma unroll
        for (int i = 0; i < 4; ++i) {
            int idx = tid + i * 256;
            int r = idx >> 3, ch = idx & 7;
            uint32_t off = SWZ((uint32_t)(r * 128 + ch * 16));
            const size_t ga = (size_t)(m0 + r) * D_ + kb + ch * 8;
            const size_t gb = (size_t)(n0 + r) * D_ + kb + ch * 8;
            cp_async16(base + off,               g_Ah + ga);
            cp_async16(base + OPBYTES + off,     g_Al + ga);
            cp_async16(base + 2 * OPBYTES + off, g_Wh + gb);
            cp_async16(base + 3 * OPBYTES + off, g_Wl + gb);
        }
    };

    float acc[4][4][4];
    #pragma unroll
    for (int mt = 0; mt < 4; ++mt)
        #pragma unroll
        for (int nt = 0; nt < 4; ++nt)
            #pragma unroll
            for (int r = 0; r < 4; ++r) acc[mt][nt][r] = 0.f;

    const int a_row = wm * 64 + (lane & 15);
    const int a_kb  = (lane >> 4) * 16;
    const int b_row = wn * 32 + ((lane >> 4) & 1) * 8 + (lane & 7);
    const int b_kb  = ((lane >> 3) & 1) * 16;

    load_chunk(0, 0);
    cp_commit(); cp_wait0();
    __syncthreads();

    for (int kt = 0; kt < NCHUNK; ++kt) {
        const int st = kt & 1;
        if (kt + 1 < NCHUNK) { load_chunk(kt + 1, st ^ 1); cp_commit(); }

        const uint32_t base = sb + st * STAGE_BYTES;
        #pragma unroll
        for (int ks = 0; ks < 4; ++ks) {
            uint32_t ah[4][4], al[4][4], bh[2][4], bl[2][4];
            #pragma unroll
            for (int mt = 0; mt < 4; ++mt) {
                uint32_t off = SWZ((uint32_t)((a_row + mt * 16) * 128 + ks * 32 + a_kb));
                ldsm_x4(ah[mt], base + off);
                ldsm_x4(al[mt], base + OPBYTES + off);
            }
            #pragma unroll
            for (int nt2 = 0; nt2 < 2; ++nt2) {
                uint32_t off = SWZ((uint32_t)((b_row + nt2 * 16) * 128 + ks * 32 + b_kb));
                ldsm_x4(bh[nt2], base + 2 * OPBYTES + off);
                ldsm_x4(bl[nt2], base + 3 * OPBYTES + off);
            }
            #pragma unroll
            for (int mt = 0; mt < 4; ++mt)
                #pragma unroll
                for (int nt = 0; nt < 4; ++nt) {
                    const uint32_t* ph = &bh[nt >> 1][(nt & 1) * 2];
                    const uint32_t* pl = &bl[nt >> 1][(nt & 1) * 2];
                    mma_bf16(acc[mt][nt], ah[mt], ph);
                    mma_bf16(acc[mt][nt], ah[mt], pl);
                    mma_bf16(acc[mt][nt], al[mt], ph);
                }
        }
        if (kt + 1 < NCHUNK) cp_wait0();
        __syncthreads();
    }

    // Epilogue: bias add, split to bf16 hi/lo, store.
    const int grp = lane >> 2, qc = (lane & 3) * 2;
    #pragma unroll
    for (int mt = 0; mt < 4; ++mt) {
        const int r0 = m0 + wm * 64 + mt * 16 + grp;
        #pragma unroll
        for (int nt = 0; nt < 4; ++nt) {
            const int col = n0 + wn * 32 + nt * 8 + qc;
            const float2 bv = *(const float2*)(bias + col);
            float o0 = acc[mt][nt][0] + bv.x, o1 = acc[mt][nt][1] + bv.y;
            float o2 = acc[mt][nt][2] + bv.x, o3 = acc[mt][nt][3] + bv.y;
            uint32_t h2, l2;
            size_t off0 = (size_t)r0 * N3_ + col;
            split2(o0, o1, h2, l2);
            *(uint32_t*)(g_kqvh + off0) = h2;
            *(uint32_t*)(g_kqvl + off0) = l2;
            size_t off1 = off0 + 8 * (size_t)N3_;
            split2(o2, o3, h2, l2);
            *(uint32_t*)(g_kqvh + off1) = h2;
            *(uint32_t*)(g_kqvl + off1) = l2;
        }
    }
}

// ============================================================================
// Tensor-core flash attention, 2 CTAs/SM.
// Single-buffered K and V with split cp.async groups:
//   K(kt+1) issued right after score(kt) (overlaps epilogue+PV),
//   V(kt+1) issued right after PV(kt)   (overlaps next score).
// wait_group 1 at loop top = K ready while V group may still be in flight.
// ============================================================================
#define BQ 128
#define BK 64
#define NKT (S_ / BK)     // 32

// smem byte offsets
#define QH_OFF 0
#define QL_OFF 16384
#define KH_OFF 32768
#define KL_OFF 40960
#define VH_OFF 49152
#define VL_OFF 57344
#define PH_OFF 65536
#define PL_OFF 81920
#define MK_OFF 98304      // + (kt&1)*256
#define DEN_OFF 98816     // float[4][128]
#define ATTN_SMEM 100864

__global__ __launch_bounds__(256, 2) void attn_mma_kernel(
    const float* __restrict__ masks, float* __restrict__ out)
{
    extern __shared__ char smem[];
    const uint32_t sb = smem_u32(smem);
    const int tid = threadIdx.x, lane = tid & 31, wid = tid >> 5;
    const int wm = wid & 1, wn = wid >> 1;
    const int b = blockIdx.z, h = blockIdx.y;
    const int q0 = blockIdx.x * BQ;
    const int grp = lane >> 2, qc = (lane & 3) * 2;

    // fragment address pieces
    const int a_row = wm * 64 + (lane & 15);
    const int a_kb  = (lane >> 4) * 16;
    const int bk_row = wn * 16 + ((lane >> 4) & 1) * 8 + (lane & 7);  // keys 0..63
    const int bk_kb  = ((lane >> 3) & 1) * 16;
    const int v_row  = ((lane >> 3) & 1) * 8 + (lane & 7);            // + ks*16
    const int v_col  = (wn * 16 + ((lane >> 4) & 1) * 8) * 2;         // dd bytes

    auto load_k = [&](int kt2) {
        const size_t tok0 = (size_t)(b * S_) + kt2 * BK;
        #pragma unroll
        for (int i = 0; i < 2; ++i) {
            int idx = tid + i * 256;
            int r = idx >> 3, ch = idx & 7;
            uint32_t off = SWZ((uint32_t)(r * 128 + ch * 16));
            size_t g = (tok0 + r) * N3_ + h * HD_ + ch * 8;
            cp_async16(sb + KH_OFF + off, g_kqvh + g);
            cp_async16(sb + KL_OFF + off, g_kqvl + g);
        }
        if (tid < BK)
            cp_async4(sb + MK_OFF + (kt2 & 1) * 256 + tid * 4,
                      masks + (size_t)b * S_ + kt2 * BK + tid);
    };
    auto load_v = [&](int kt2) {
        const size_t tok0 = (size_t)(b * S_) + kt2 * BK;
        #pragma unroll
        for (int i = 0; i < 2; ++i) {
            int idx = tid + i * 256;
            int r = idx >> 3, ch = idx & 7;
            uint32_t off = SWZ((uint32_t)(r * 128 + ch * 16));
            size_t g = (tok0 + r) * N3_ + h * HD_ + ch * 8 + 2 * D_;
            cp_async16(sb + VH_OFF + off, g_kqvh + g);
            cp_async16(sb + VL_OFF + off, g_kqvl + g);
        }
    };

    // Prologue: Q + K(0) + mask(0) as group 1, V(0) as group 2.
    #pragma unroll
    for (int i = 0; i < 4; ++i) {
        int idx = tid + i * 256;
        int r = idx >> 3, ch = idx & 7;
        uint32_t off = SWZ((uint32_t)(r * 128 + ch * 16));
        size_t g = (size_t)(b * S_ + q0 + r) * N3_ + D_ + h * HD_ + ch * 8;
        cp_async16(sb + QH_OFF + off, g_kqvh + g);
        cp_async16(sb + QL_OFF + off, g_kqvl + g);
    }
    load_k(0);
    cp_commit();
    load_v(0);
    cp_commit();

    float acc_o[4][2][4];
    #pragma unroll
    for (int mt = 0; mt < 4; ++mt)
        #pragma unroll
        for (int nt = 0; nt < 2; ++nt)
            #pragma unroll
            for (int r = 0; r < 4; ++r) acc_o[mt][nt][r] = 0.f;
    float den[4][2];
    #pragma unroll
    for (int mt = 0; mt < 4; ++mt) { den[mt][0] = 0.f; den[mt][1] = 0.f; }

    for (int kt = 0; kt < NKT; ++kt) {
        // K(kt) (+Q on first iter) ready; V group may still be in flight.
        cp_wait1();
        __syncthreads();

        // ---- score GEMM: S[128 q][64 k] over d=64 ----
        float acc_s[4][2][4];
        #pragma unroll
        for (int mt = 0; mt < 4; ++mt)
            #pragma unroll
            for (int nt = 0; nt < 2; ++nt)
                #pragma unroll
                for (int r = 0; r < 4; ++r) acc_s[mt][nt][r] = 0.f;

        #pragma unroll
        for (int ks = 0; ks < 4; ++ks) {
            uint32_t bkh[4], bkl[4];
            {
                uint32_t off = SWZ((uint32_t)(bk_row * 128 + ks * 32 + bk_kb));
                ldsm_x4(bkh, sb + KH_OFF + off);
                ldsm_x4(bkl, sb + KL_OFF + off);
            }
            #pragma unroll
            for (int mt = 0; mt < 4; ++mt) {
                uint32_t aqh[4], aql[4];
                uint32_t off = SWZ((uint32_t)((a_row + mt * 16) * 128 + ks * 32 + a_kb));
                ldsm_x4(aqh, sb + QH_OFF + off);
                ldsm_x4(aql, sb + QL_OFF + off);
                #pragma unroll
                for (int nt = 0; nt < 2; ++nt) {
                    mma_bf16(acc_s[mt][nt], aqh, &bkh[nt * 2]);
                    mma_bf16(acc_s[mt][nt], aqh, &bkl[nt * 2]);
                    mma_bf16(acc_s[mt][nt], aql, &bkh[nt * 2]);
                }
            }
        }

        // Done reading K -> safe to overwrite with K(kt+1); overlaps epilogue+PV.
        __syncthreads();
        if (kt + 1 < NKT) { load_k(kt + 1); cp_commit(); }

        // ---- epilogue: p = exp(clip(elu(s))) * mask_k; den accum; P -> smem ----
        const float* mk = (const float*)(smem + MK_OFF + (kt & 1) * 256);
        char* phs = smem + PH_OFF;
        char* pls = smem + PL_OFF;
        #pragma unroll
        for (int mt = 0; mt < 4; ++mt) {
            const int r = wm * 64 + mt * 16 + grp;
            #pragma unroll
            for (int nt = 0; nt < 2; ++nt) {
                const int c = wn * 16 + nt * 8 + qc;
                float m0 = mk[c], m1 = mk[c + 1];
                float p0 = elu_exp(acc_s[mt][nt][0]) * m0;
                float p1 = elu_exp(acc_s[mt][nt][1]) * m1;
                float p2 = elu_exp(acc_s[mt][nt][2]) * m0;
                float p3 = elu_exp(acc_s[mt][nt][3]) * m1;
                den[mt][0] += p0 + p1;
                den[mt][1] += p2 + p3;
                uint32_t h2, l2;
                uint32_t o0 = SWZ((uint32_t)(r * 128 + c * 2));
                split2(p0, p1, h2, l2);
                *(uint32_t*)(phs + o0) = h2;
                *(uint32_t*)(pls + o0) = l2;
                uint32_t o1 = SWZ((uint32_t)((r + 8) * 128 + c * 2));
                split2(p2, p3, h2, l2);
                *(uint32_t*)(phs + o1) = h2;
                *(uint32_t*)(pls + o1) = l2;
            }
        }

        // Need: P visible to all warps AND V(kt) arrived.
        if (kt + 1 < NKT) cp_wait1(); else cp_wait0();
        __syncthreads();

        // ---- PV GEMM: O[128 q][64 d] += P[128][64] @ V[64][64] ----
        #pragma unroll
        for (int ks = 0; ks < 4; ++ks) {
            uint32_t bvh[4], bvl[4];
            {
                uint32_t off = SWZ((uint32_t)((ks * 16 + v_row) * 128 + v_col));
                ldsm_x4_t(bvh, sb + VH_OFF + off);
                ldsm_x4_t(bvl, sb + VL_OFF + off);
            }
            #pragma unroll
            for (int mt = 0; mt < 4; ++mt) {
                uint32_t aph[4], apl[4];
                uint32_t off = SWZ((uint32_t)((a_row + mt * 16) * 128 + ks * 32 + a_kb));
                ldsm_x4(aph, sb + PH_OFF + off);
                ldsm_x4(apl, sb + PL_OFF + off);
                #pragma unroll
                for (int nt = 0; nt < 2; ++nt) {
                    mma_bf16(acc_o[mt][nt], aph, &bvh[nt * 2]);
                    mma_bf16(acc_o[mt][nt], aph, &bvl[nt * 2]);
                    mma_bf16(acc_o[mt][nt], apl, &bvh[nt * 2]);
                }
            }
        }

        // Done reading V -> safe to overwrite with V(kt+1); overlaps next score.
        if (kt + 1 < NKT) {
            __syncthreads();
            load_v(kt + 1);
            cp_commit();
        }
    }

    // ---- denominator reduce + writeback ----
    #pragma unroll
    for (int mt = 0; mt < 4; ++mt)
        #pragma unroll
        for (int r01 = 0; r01 < 2; ++r01) {
            float v = den[mt][r01];
            v += __shfl_xor_sync(0xffffffffu, v, 1);
            v += __shfl_xor_sync(0xffffffffu, v, 2);
            den[mt][r01] = v;
        }
    float* den_s = (float*)(smem + DEN_OFF);
    __syncthreads();
    if ((lane & 3) == 0) {
        #pragma unroll
        for (int mt = 0; mt < 4; ++mt) {
            int r = wm * 64 + mt * 16 + grp;
            den_s[wn * 128 + r]     = den[mt][0];
            den_s[wn * 128 + r + 8] = den[mt][1];
        }
    }
    __syncthreads();

    #pragma unroll
    for (int mt = 0; mt < 4; ++mt) {
        const int r = wm * 64 + mt * 16 + grp;
        float d0 = den_s[r] + den_s[128 + r] + den_s[256 + r] + den_s[384 + r];
        float d1 = den_s[r + 8] + den_s[128 + r + 8] + den_s[256 + r + 8] + den_s[384 + r + 8];
        float s0 = masks[(size_t)b * S_ + q0 + r]     / d0;
        float s1 = masks[(size_t)b * S_ + q0 + r + 8] / d1;
        #pragma unroll
        for (int nt = 0; nt < 2; ++nt) {
            const int c = wn * 16 + nt * 8 + qc;
            float* p0 = out + (size_t)(b * S_ + q0 + r) * D_ + h * HD_ + c;
            *(float2*)p0 = make_float2(acc_o[mt][nt][0] * s0, acc_o[mt][nt][1] * s0);
            *(float2*)(p0 + 8 * (size_t)D_) =
                make_float2(acc_o[mt][nt][2] * s1, acc_o[mt][nt][3] * s1);
        }
    }
}

// ============================================================================
// Launch
// ============================================================================
extern "C" void kernel_launch(void* const* d_in, const int* in_sizes, int n_in,
                              void* d_out, int out_size)
{
    const float *inp = nullptr, *msk = nullptr, *W = nullptr, *bias = nullptr;
    for (int i = 0; i < n_in; ++i) {
        switch (in_sizes[i]) {
            case M_ * D_:   inp  = (const float*)d_in[i]; break;  // inputs  [2,2048,1024]
            case B_ * S_:   msk  = (const float*)d_in[i]; break;  // masks   [2,2048]
            case D_ * N3_:  W    = (const float*)d_in[i]; break;  // W       [1024,3072]
            case N3_:       bias = (const float*)d_in[i]; break;  // b       [3072]
        }
    }

    cudaFuncSetAttribute(gemm_mma_kernel,
                         cudaFuncAttributeMaxDynamicSharedMemorySize, GEMM_SMEM);
    cudaFuncSetAttribute(attn_mma_kernel,
                         cudaFuncAttributeMaxDynamicSharedMemorySize, ATTN_SMEM);

    split_a_kernel<<<(M_ * D_) / 1024, 256>>>(inp);
    split_w_kernel<<<dim3(N3_ / 32, D_ / 32), dim3(32, 8)>>>(W);

    dim3 g1(N3_ / GN, M_ / GM);            // (24, 32)
    gemm_mma_kernel<<<g1, 256, GEMM_SMEM>>>(bias);

    dim3 g2(S_ / BQ, H_, B_);              // (16, 16, 2)
    attn_mma_kernel<<<g2, 256, ATTN_SMEM>>>(msk, (float*)d_out);
}

// round 7
// speedup vs baseline: 4.9020x; 1.1037x over previous
#include <cuda_runtime.h>
#include <cuda_bf16.h>
#include <cstdint>

// Problem constants
#define B_  2
#define S_  2048
#define D_  1024
#define H_  16
#define HD_ 64
#define N3_ 3072
#define M_  (B_ * S_)   // 4096

// bf16 hi/lo pairs: split inputs for projection GEMM, and split KQV output.
__device__ __nv_bfloat16 g_Ah[(size_t)M_ * D_];
__device__ __nv_bfloat16 g_Al[(size_t)M_ * D_];
__device__ __nv_bfloat16 g_Wh[(size_t)N3_ * D_];   // W transposed: [n][k]
__device__ __nv_bfloat16 g_Wl[(size_t)N3_ * D_];
__device__ __nv_bfloat16 g_kqvh[(size_t)M_ * N3_]; // [token][3072]: K|Q|V
__device__ __nv_bfloat16 g_kqvl[(size_t)M_ * N3_];

typedef unsigned long long ull;

// ===================== helpers =====================
__device__ __forceinline__ uint32_t smem_u32(const void* p) {
    uint32_t a;
    asm("{ .reg .u64 t; cvta.to.shared.u64 t, %1; cvt.u32.u64 %0, t; }" : "=r"(a) : "l"(p));
    return a;
}
#define SWZ(o) ((o) ^ (((o) >> 3) & 0x70))

__device__ __forceinline__ void cp_async16(uint32_t dst, const void* src) {
    asm volatile("cp.async.cg.shared.global [%0], [%1], 16;" :: "r"(dst), "l"(src));
}
__device__ __forceinline__ void cp_async4(uint32_t dst, const void* src) {
    asm volatile("cp.async.ca.shared.global [%0], [%1], 4;" :: "r"(dst), "l"(src));
}
__device__ __forceinline__ void cp_commit() { asm volatile("cp.async.commit_group;" ::: "memory"); }
__device__ __forceinline__ void cp_wait0()  { asm volatile("cp.async.wait_group 0;" ::: "memory"); }

__device__ __forceinline__ void ldsm_x4(uint32_t* r, uint32_t addr) {
    asm volatile("ldmatrix.sync.aligned.m8n8.x4.shared.b16 {%0,%1,%2,%3}, [%4];"
        : "=r"(r[0]), "=r"(r[1]), "=r"(r[2]), "=r"(r[3]) : "r"(addr));
}
__device__ __forceinline__ void ldsm_x4_t(uint32_t* r, uint32_t addr) {
    asm volatile("ldmatrix.sync.aligned.m8n8.x4.trans.shared.b16 {%0,%1,%2,%3}, [%4];"
        : "=r"(r[0]), "=r"(r[1]), "=r"(r[2]), "=r"(r[3]) : "r"(addr));
}
__device__ __forceinline__ void mma_bf16(float* d, const uint32_t* a, const uint32_t* b) {
    asm volatile("mma.sync.aligned.m16n8k16.row.col.f32.bf16.bf16.f32 "
        "{%0,%1,%2,%3}, {%4,%5,%6,%7}, {%8,%9}, {%0,%1,%2,%3};"
        : "+f"(d[0]), "+f"(d[1]), "+f"(d[2]), "+f"(d[3])
        : "r"(a[0]), "r"(a[1]), "r"(a[2]), "r"(a[3]), "r"(b[0]), "r"(b[1]));
}

// pack two fp32 into bf16 hi-pair + lo-pair (residual)
__device__ __forceinline__ void split2(float a, float b, uint32_t& h2, uint32_t& l2) {
    __nv_bfloat162 h;
    h.x = __float2bfloat16(a); h.y = __float2bfloat16(b);
    __nv_bfloat162 l;
    l.x = __float2bfloat16(a - __bfloat162float(h.x));
    l.y = __float2bfloat16(b - __bfloat162float(h.y));
    h2 = *(uint32_t*)&h; l2 = *(uint32_t*)&l;
}

__device__ __forceinline__ float elu_exp(float u) {
    float e = u > 0.f ? fminf(u, 10.f) : (__expf(u) - 1.f);
    return __expf(e);
}

// ============================================================================
// Split kernels: fp32 -> (hi, lo) bf16 pair
// ============================================================================
__global__ void split_a_kernel(const float* __restrict__ in) {
    size_t i = ((size_t)blockIdx.x * 256 + threadIdx.x) * 4;
    float4 v = *(const float4*)(in + i);
    float x[4] = {v.x, v.y, v.z, v.w};
    #pragma unroll
    for (int j = 0; j < 4; ++j) {
        __nv_bfloat16 h = __float2bfloat16(x[j]);
        g_Ah[i + j] = h;
        g_Al[i + j] = __float2bfloat16(x[j] - __bfloat162float(h));
    }
}

__global__ void split_w_kernel(const float* __restrict__ W) {
    __shared__ float t[32][33];
    int tx = threadIdx.x, ty = threadIdx.y;
    int n0 = blockIdx.x * 32, k0 = blockIdx.y * 32;
    #pragma unroll
    for (int i = 0; i < 4; ++i)
        t[ty + i * 8][tx] = W[(size_t)(k0 + ty + i * 8) * N3_ + n0 + tx];
    __syncthreads();
    #pragma unroll
    for (int i = 0; i < 4; ++i) {
        float x = t[tx][ty + i * 8];
        size_t o = (size_t)(n0 + ty + i * 8) * D_ + k0 + tx;
        __nv_bfloat16 h = __float2bfloat16(x);
        g_Wh[o] = h;
        g_Wl[o] = __float2bfloat16(x - __bfloat162float(h));
    }
}

// ============================================================================
// HMMA projection GEMM: kqv = A @ W + bias, output written as bf16 hi/lo.
// CTA 128x128, K-chunk 64, single-buffered 64KB stage -> 2 CTAs/SM.
// ============================================================================
#define GM 128
#define GN 128
#define GKC 64
#define NCHUNK (D_ / GKC)          // 16
#define OPBYTES (GM * GKC * 2)     // 16384 per operand tile
#define STAGE_BYTES (4 * OPBYTES)  // 65536
#define GEMM_SMEM STAGE_BYTES

__global__ __launch_bounds__(256, 2) void gemm_mma_kernel(const float* __restrict__ bias)
{
    extern __shared__ char smem[];
    const uint32_t sb = smem_u32(smem);
    const int tid = threadIdx.x, lane = tid & 31, wid = tid >> 5;
    const int wm = wid & 1, wn = wid >> 1;
    const int m0 = blockIdx.y * GM, n0 = blockIdx.x * GN;

    auto load_chunk = [&](int c) {
        const size_t kb = (size_t)c * GKC;
        #pragma unroll
        for (int i = 0; i < 4; ++i) {
            int idx = tid + i * 256;
            int r = idx >> 3, ch = idx & 7;
            uint32_t off = SWZ((uint32_t)(r * 128 + ch * 16));
            const size_t ga = (size_t)(m0 + r) * D_ + kb + ch * 8;
            const size_t gb = (size_t)(n0 + r) * D_ + kb + ch * 8;
            cp_async16(sb + off,               g_Ah + ga);
            cp_async16(sb + OPBYTES + off,     g_Al + ga);
            cp_async16(sb + 2 * OPBYTES + off, g_Wh + gb);
            cp_async16(sb + 3 * OPBYTES + off, g_Wl + gb);
        }
    };

    float acc[4][4][4];
    #pragma unroll
    for (int mt = 0; mt < 4; ++mt)
        #pragma unroll
        for (int nt = 0; nt < 4; ++nt)
            #pragma unroll
            for (int r = 0; r < 4; ++r) acc[mt][nt][r] = 0.f;

    const int a_row = wm * 64 + (lane & 15);
    const int a_kb  = (lane >> 4) * 16;
    const int b_row = wn * 32 + ((lane >> 4) & 1) * 8 + (lane & 7);
    const int b_kb  = ((lane >> 3) & 1) * 16;

    load_chunk(0);
    cp_commit();

    for (int kt = 0; kt < NCHUNK; ++kt) {
        cp_wait0();
        __syncthreads();

        #pragma unroll
        for (int ks = 0; ks < 4; ++ks) {
            uint32_t bh[2][4], bl[2][4];
            #pragma unroll
            for (int nt2 = 0; nt2 < 2; ++nt2) {
                uint32_t off = SWZ((uint32_t)((b_row + nt2 * 16) * 128 + ks * 32 + b_kb));
                ldsm_x4(bh[nt2], sb + 2 * OPBYTES + off);
                ldsm_x4(bl[nt2], sb + 3 * OPBYTES + off);
            }
            #pragma unroll
            for (int mt = 0; mt < 4; ++mt) {
                uint32_t ah[4], al[4];
                uint32_t off = SWZ((uint32_t)((a_row + mt * 16) * 128 + ks * 32 + a_kb));
                ldsm_x4(ah, sb + off);
                ldsm_x4(al, sb + OPBYTES + off);
                #pragma unroll
                for (int nt = 0; nt < 4; ++nt) {
                    const uint32_t* ph = &bh[nt >> 1][(nt & 1) * 2];
                    const uint32_t* pl = &bl[nt >> 1][(nt & 1) * 2];
                    mma_bf16(acc[mt][nt], ah, ph);
                    mma_bf16(acc[mt][nt], ah, pl);
                    mma_bf16(acc[mt][nt], al, ph);
                }
            }
        }
        __syncthreads();
        if (kt + 1 < NCHUNK) { load_chunk(kt + 1); cp_commit(); }
    }

    // Epilogue: bias add, split to bf16 hi/lo, store.
    const int grp = lane >> 2, qc = (lane & 3) * 2;
    #pragma unroll
    for (int mt = 0; mt < 4; ++mt) {
        const int r0 = m0 + wm * 64 + mt * 16 + grp;
        #pragma unroll
        for (int nt = 0; nt < 4; ++nt) {
            const int col = n0 + wn * 32 + nt * 8 + qc;
            const float2 bv = *(const float2*)(bias + col);
            float o0 = acc[mt][nt][0] + bv.x, o1 = acc[mt][nt][1] + bv.y;
            float o2 = acc[mt][nt][2] + bv.x, o3 = acc[mt][nt][3] + bv.y;
            uint32_t h2, l2;
            size_t off0 = (size_t)r0 * N3_ + col;
            split2(o0, o1, h2, l2);
            *(uint32_t*)(g_kqvh + off0) = h2;
            *(uint32_t*)(g_kqvl + off0) = l2;
            size_t off1 = off0 + 8 * (size_t)N3_;
            split2(o2, o3, h2, l2);
            *(uint32_t*)(g_kqvh + off1) = h2;
            *(uint32_t*)(g_kqvl + off1) = l2;
        }
    }
}

// ============================================================================
// Tensor-core flash attention, FA2-style register P.
// 8 warps, each owns 16 q-rows x all 64 keys. Score accumulator fragments are
// re-packed in registers (bf16 hi/lo) as the A operand of the PV mma -> no P
// smem round-trip, no cross-warp denominator reduce. K/V double-buffered:
// ONE __syncthreads + ONE cp.wait per key tile.
// ============================================================================
#define BQ 128
#define BK 64
#define NKT (S_ / BK)     // 32

// smem byte offsets (96.5 KB total -> 2 CTAs/SM)
#define QH_OFF 0
#define QL_OFF 16384
#define KH_OFF 32768      // + st*8192
#define KL_OFF 49152      // + st*8192
#define VH_OFF 65536      // + st*8192
#define VL_OFF 81920      // + st*8192
#define MK_OFF 98304      // + st*256
#define ATTN_SMEM 98816

__global__ __launch_bounds__(256, 2) void attn_mma_kernel(
    const float* __restrict__ masks, float* __restrict__ out)
{
    extern __shared__ char smem[];
    const uint32_t sb = smem_u32(smem);
    const int tid = threadIdx.x, lane = tid & 31, wid = tid >> 5;
    const int b = blockIdx.z, h = blockIdx.y;
    const int q0 = blockIdx.x * BQ;
    const int grp = lane >> 2, qc = (lane & 3) * 2;

    // fragment address pieces
    const int a_row = wid * 16 + (lane & 15);                 // Q rows for this warp
    const int a_kb  = (lane >> 4) * 16;
    const int bk_sub = ((lane >> 4) & 1) * 8 + (lane & 7);    // + nt2*16 (key rows)
    const int bk_kb  = ((lane >> 3) & 1) * 16;
    const int v_row  = ((lane >> 3) & 1) * 8 + (lane & 7);    // + ks*16
    const int v_cb   = ((lane >> 4) & 1) * 16;                // + nt2*32 (d bytes)

    auto load_kv = [&](int kt2, int st2) {
        const size_t tok0 = (size_t)(b * S_) + kt2 * BK;
        #pragma unroll
        for (int i = 0; i < 2; ++i) {
            int idx = tid + i * 256;
            int r = idx >> 3, ch = idx & 7;
            uint32_t off = SWZ((uint32_t)(r * 128 + ch * 16)) + st2 * 8192;
            size_t g = (tok0 + r) * N3_ + h * HD_ + ch * 8;
            cp_async16(sb + KH_OFF + off, g_kqvh + g);
            cp_async16(sb + KL_OFF + off, g_kqvl + g);
            cp_async16(sb + VH_OFF + off, g_kqvh + g + 2 * D_);
            cp_async16(sb + VL_OFF + off, g_kqvl + g + 2 * D_);
        }
        if (tid < BK)
            cp_async4(sb + MK_OFF + (kt2 & 1) * 256 + tid * 4,
                      masks + (size_t)b * S_ + kt2 * BK + tid);
    };

    // Prologue: Q tile + K/V(0) + mask(0), one commit group.
    #pragma unroll
    for (int i = 0; i < 4; ++i) {
        int idx = tid + i * 256;
        int r = idx >> 3, ch = idx & 7;
        uint32_t off = SWZ((uint32_t)(r * 128 + ch * 16));
        size_t g = (size_t)(b * S_ + q0 + r) * N3_ + D_ + h * HD_ + ch * 8;
        cp_async16(sb + QH_OFF + off, g_kqvh + g);
        cp_async16(sb + QL_OFF + off, g_kqvl + g);
    }
    load_kv(0, 0);
    cp_commit();

    float acc_o[8][4];
    #pragma unroll
    for (int nt = 0; nt < 8; ++nt)
        #pragma unroll
        for (int r = 0; r < 4; ++r) acc_o[nt][r] = 0.f;
    float den0 = 0.f, den1 = 0.f;

    for (int kt = 0; kt < NKT; ++kt) {
        const int st = kt & 1;
        // K/V/mask(kt) arrived; all warps aligned.
        cp_wait0();
        __syncthreads();
        // Prefetch next tile into the other buffer (overlaps this tile's math).
        if (kt + 1 < NKT) { load_kv(kt + 1, st ^ 1); cp_commit(); }

        // ---- score GEMM: S[16 q][64 k] per warp over d=64 ----
        float acc_s[8][4];
        #pragma unroll
        for (int nt = 0; nt < 8; ++nt)
            #pragma unroll
            for (int r = 0; r < 4; ++r) acc_s[nt][r] = 0.f;

        #pragma unroll
        for (int ks = 0; ks < 4; ++ks) {
            uint32_t aqh[4], aql[4];
            {
                uint32_t off = SWZ((uint32_t)(a_row * 128 + ks * 32 + a_kb));
                ldsm_x4(aqh, sb + QH_OFF + off);
                ldsm_x4(aql, sb + QL_OFF + off);
            }
            #pragma unroll
            for (int nt2 = 0; nt2 < 4; ++nt2) {
                uint32_t bkh[4], bkl[4];
                uint32_t off = SWZ((uint32_t)((nt2 * 16 + bk_sub) * 128 + ks * 32 + bk_kb))
                               + st * 8192;
                ldsm_x4(bkh, sb + KH_OFF + off);
                ldsm_x4(bkl, sb + KL_OFF + off);
                #pragma unroll
                for (int hf = 0; hf < 2; ++hf) {
                    float* d = acc_s[nt2 * 2 + hf];
                    mma_bf16(d, aqh, &bkh[hf * 2]);
                    mma_bf16(d, aqh, &bkl[hf * 2]);
                    mma_bf16(d, aql, &bkh[hf * 2]);
                }
            }
        }

        // ---- epilogue in registers: p = exp(clip(elu(s)))*mask_k ----
        // Repack score fragments as PV A-operand fragments (bf16 hi/lo).
        const float* mk = (const float*)(smem + MK_OFF + st * 256);
        uint32_t pfh[4][4], pfl[4][4];
        #pragma unroll
        for (int nt = 0; nt < 8; ++nt) {
            const int c = nt * 8 + qc;
            float m0 = mk[c], m1 = mk[c + 1];
            float p0 = elu_exp(acc_s[nt][0]) * m0;
            float p1 = elu_exp(acc_s[nt][1]) * m1;
            float p2 = elu_exp(acc_s[nt][2]) * m0;
            float p3 = elu_exp(acc_s[nt][3]) * m1;
            den0 += p0 + p1;
            den1 += p2 + p3;
            const int ks = nt >> 1, bi = (nt & 1) * 2;
            split2(p0, p1, pfh[ks][bi + 0], pfl[ks][bi + 0]);
            split2(p2, p3, pfh[ks][bi + 1], pfl[ks][bi + 1]);
        }

        // ---- PV GEMM: O[16 q][64 d] += P[16][64] @ V[64][64] ----
        #pragma unroll
        for (int ks = 0; ks < 4; ++ks) {
            #pragma unroll
            for (int nt2 = 0; nt2 < 4; ++nt2) {
                uint32_t bvh[4], bvl[4];
                uint32_t off = SWZ((uint32_t)((ks * 16 + v_row) * 128 + nt2 * 32 + v_cb))
                               + st * 8192;
                ldsm_x4_t(bvh, sb + VH_OFF + off);
                ldsm_x4_t(bvl, sb + VL_OFF + off);
                #pragma unroll
                for (int hf = 0; hf < 2; ++hf) {
                    float* d = acc_o[nt2 * 2 + hf];
                    mma_bf16(d, pfh[ks], &bvh[hf * 2]);
                    mma_bf16(d, pfh[ks], &bvl[hf * 2]);
                    mma_bf16(d, pfl[ks], &bvh[hf * 2]);
                }
            }
        }
        // Next iteration's cp_wait0+sync protects buffer st^1 before overwrite of st.
    }

    // ---- denominator reduce (within warp: lane bits 0,1) + writeback ----
    den0 += __shfl_xor_sync(0xffffffffu, den0, 1);
    den0 += __shfl_xor_sync(0xffffffffu, den0, 2);
    den1 += __shfl_xor_sync(0xffffffffu, den1, 1);
    den1 += __shfl_xor_sync(0xffffffffu, den1, 2);

    const int r0 = wid * 16 + grp;
    const int r1 = r0 + 8;
    float s0 = masks[(size_t)b * S_ + q0 + r0] / den0;
    float s1 = masks[(size_t)b * S_ + q0 + r1] / den1;
    #pragma unroll
    for (int nt = 0; nt < 8; ++nt) {
        const int c = nt * 8 + qc;
        float* p0 = out + (size_t)(b * S_ + q0 + r0) * D_ + h * HD_ + c;
        float* p1 = out + (size_t)(b * S_ + q0 + r1) * D_ + h * HD_ + c;
        *(float2*)p0 = make_float2(acc_o[nt][0] * s0, acc_o[nt][1] * s0);
        *(float2*)p1 = make_float2(acc_o[nt][2] * s1, acc_o[nt][3] * s1);
    }
}

// ============================================================================
// Launch
// ============================================================================
extern "C" void kernel_launch(void* const* d_in, const int* in_sizes, int n_in,
                              void* d_out, int out_size)
{
    const float *inp = nullptr, *msk = nullptr, *W = nullptr, *bias = nullptr;
    for (int i = 0; i < n_in; ++i) {
        switch (in_sizes[i]) {
            case M_ * D_:   inp  = (const float*)d_in[i]; break;  // inputs  [2,2048,1024]
            case B_ * S_:   msk  = (const float*)d_in[i]; break;  // masks   [2,2048]
            case D_ * N3_:  W    = (const float*)d_in[i]; break;  // W       [1024,3072]
            case N3_:       bias = (const float*)d_in[i]; break;  // b       [3072]
        }
    }

    cudaFuncSetAttribute(gemm_mma_kernel,
                         cudaFuncAttributeMaxDynamicSharedMemorySize, GEMM_SMEM);
    cudaFuncSetAttribute(attn_mma_kernel,
                         cudaFuncAttributeMaxDynamicSharedMemorySize, ATTN_SMEM);

    split_a_kernel<<<(M_ * D_) / 1024, 256>>>(inp);
    split_w_kernel<<<dim3(N3_ / 32, D_ / 32), dim3(32, 8)>>>(W);

    dim3 g1(N3_ / GN, M_ / GM);            // (24, 32)
    gemm_mma_kernel<<<g1, 256, GEMM_SMEM>>>(bias);

    dim3 g2(S_ / BQ, H_, B_);              // (16, 16, 2)
    attn_mma_kernel<<<g2, 256, ATTN_SMEM>>>(msk, (float*)d_out);
}